// round 7
// baseline (speedup 1.0000x reference)
#include <cuda_runtime.h>
#include <cuda_bf16.h>
#include <cstdint>

#define TT   1024
#define BSZ  64
#define DD   256
#define HH   256
#define G4   1024            // 4*H
#define NBLK 128             // persistent recurrent blocks
#define TBH  (TT*BSZ*HH)
#define BH   (BSZ*HH)
#define FPAD 64              // flag padding: 64 uints = 256B stride

typedef unsigned long long ull;

// Scratch (device globals: no runtime allocation allowed)
__device__ float    g_Z[(size_t)TT * BSZ * G4];   // [t][b][gate*256+u]  (256 MB)
__device__ float    g_h[2][BSZ * HH];             // hidden [b][k], double-buffered
__device__ unsigned g_flags[NBLK * FPAD];         // per-block step flags (256B apart)

#define FMA_F32X2(d, a, b, c) \
    asm("fma.rn.f32x2 %0, %1, %2, %3;" : "=l"(d) : "l"(a), "l"(b), "l"(c))
#define ADD_F32X2(d, a, b) \
    asm("add.rn.f32x2 %0, %1, %2;" : "=l"(d) : "l"(a), "l"(b))
#define PACK2(d, lo, hi) \
    asm("mov.b64 %0, {%1, %2};" : "=l"(d) : "f"(lo), "f"(hi))
#define UNPACK2(lo, hi, s) \
    asm("mov.b64 {%0, %1}, %2;" : "=f"(lo), "=f"(hi) : "l"(s))

// ---------------------------------------------------------------------------
// Phase 1: Z[t][b][g*256+u] = bias_g[u] + sum_k x[t][b][k] * W_g[u*512 + k]
// GEMM M=65536 (t*64+b), N=1024, K=256. BM=128, BN=128, BK=16, 8x8 tiles.
// Blocks with (x<8, y<4) also reset the 8192 flag words.
// ---------------------------------------------------------------------------
__global__ __launch_bounds__(256, 2)
void proj_kernel(const float* __restrict__ x,
                 const float* __restrict__ Wf, const float* __restrict__ bf,
                 const float* __restrict__ Wi, const float* __restrict__ bi,
                 const float* __restrict__ Wg, const float* __restrict__ bg,
                 const float* __restrict__ Wo, const float* __restrict__ bo)
{
    __shared__ float As[16 * 132];
    __shared__ float Bs[16 * 132];

    const int tid = threadIdx.x;
    if (blockIdx.y < 4) {
        int idx = (blockIdx.y * 8 + blockIdx.x) * 256 + tid;   // 32*256 = 8192
        g_flags[idx] = 0u;
    }

    const int tx  = tid & 15;
    const int ty  = tid >> 4;
    const int bm    = blockIdx.y * 128;
    const int gate  = blockIdx.x >> 1;
    const int ucol0 = (blockIdx.x & 1) * 128;

    const float* W    = (gate == 0) ? Wf : (gate == 1) ? Wi : (gate == 2) ? Wg : Wo;
    const float* bias = (gate == 0) ? bf : (gate == 1) ? bi : (gate == 2) ? bg : bo;

    float acc[8][8];
#pragma unroll
    for (int i = 0; i < 8; i++)
#pragma unroll
        for (int j = 0; j < 8; j++) acc[i][j] = 0.f;

    for (int k0 = 0; k0 < 256; k0 += 16) {
#pragma unroll
        for (int it = 0; it < 2; it++) {
            int f4  = tid + it * 256;          // 512 float4 per tile
            int row = f4 >> 2;                 // 0..127
            int kc  = (f4 & 3) << 2;           // 0,4,8,12
            float4 av = *(const float4*)(x + (size_t)(bm + row) * 256 + k0 + kc);
            As[(kc + 0) * 132 + row] = av.x;
            As[(kc + 1) * 132 + row] = av.y;
            As[(kc + 2) * 132 + row] = av.z;
            As[(kc + 3) * 132 + row] = av.w;
            float4 bv = *(const float4*)(W + (size_t)(ucol0 + row) * 512 + k0 + kc);
            Bs[(kc + 0) * 132 + row] = bv.x;
            Bs[(kc + 1) * 132 + row] = bv.y;
            Bs[(kc + 2) * 132 + row] = bv.z;
            Bs[(kc + 3) * 132 + row] = bv.w;
        }
        __syncthreads();
#pragma unroll
        for (int kk = 0; kk < 16; kk++) {
            float4 a0 = *(const float4*)&As[kk * 132 + ty * 8];
            float4 a1 = *(const float4*)&As[kk * 132 + ty * 8 + 4];
            float4 b0 = *(const float4*)&Bs[kk * 132 + tx * 8];
            float4 b1 = *(const float4*)&Bs[kk * 132 + tx * 8 + 4];
            float a[8] = {a0.x, a0.y, a0.z, a0.w, a1.x, a1.y, a1.z, a1.w};
            float b[8] = {b0.x, b0.y, b0.z, b0.w, b1.x, b1.y, b1.z, b1.w};
#pragma unroll
            for (int i = 0; i < 8; i++)
#pragma unroll
                for (int j = 0; j < 8; j++) acc[i][j] += a[i] * b[j];
        }
        __syncthreads();
    }

    float4 q0 = *(const float4*)(bias + ucol0 + tx * 8);
    float4 q1 = *(const float4*)(bias + ucol0 + tx * 8 + 4);
    float bb[8] = {q0.x, q0.y, q0.z, q0.w, q1.x, q1.y, q1.z, q1.w};

#pragma unroll
    for (int i = 0; i < 8; i++) {
        size_t m  = (size_t)(bm + ty * 8 + i);
        float* zp = g_Z + m * 1024 + gate * 256 + ucol0 + tx * 8;
        float4 v0 = {acc[i][0] + bb[0], acc[i][1] + bb[1], acc[i][2] + bb[2], acc[i][3] + bb[3]};
        float4 v1 = {acc[i][4] + bb[4], acc[i][5] + bb[5], acc[i][6] + bb[6], acc[i][7] + bb[7]};
        *(float4*)zp       = v0;
        *(float4*)(zp + 4) = v1;
    }
}

// ---------------------------------------------------------------------------
// Phase 2: persistent recurrence. 128 blocks x 512 threads.
// Block owns hidden units {2*blk, 2*blk+1} -> 8 gate cols (4 gates x 2 units).
// Sync: per-block flags (256B apart). Producer st.release its OWN flag
// (no atomic contention); consumer threads 0..127 each acquire-poll ONE
// distinct flag line, then __syncthreads. Stage h (64KB coalesced) -> SMEM,
// non-redundant register-weight FFMA2 compute, distributing butterfly fold.
// ---------------------------------------------------------------------------
__device__ __forceinline__ float sig_(float v)  { return __fdividef(1.f, 1.f + __expf(-v)); }
__device__ __forceinline__ float tanh_(float v) { return __fdividef(2.f, 1.f + __expf(-2.f * v)) - 1.f; }

#define HS_FLOATS (BSZ * HH)             // 16384 floats = 64KB
#define SMEM_FLOATS (HS_FLOATS + 8 * 65)

__global__ __launch_bounds__(512, 1)
void lstm_kernel(const float* __restrict__ Wf, const float* __restrict__ Wi,
                 const float* __restrict__ Wg, const float* __restrict__ Wo,
                 float* __restrict__ out)
{
    extern __shared__ float smem[];
    float* hs  = smem;                   // [b][k] linear copy of g_h
    float* pre = smem + HS_FLOATS;       // [c][b], stride 65

    const int tid  = threadIdx.x;
    const int blk  = blockIdx.x;
    const int u0   = blk * 2;
    const int lane = tid & 31;
    const int warp = tid >> 5;

    // ---- recurrent weights in registers, f32x2 packed over {u0, u0+1} ----
    const float* Ws[4] = {Wf, Wi, Wg, Wo};
    ull wp[4][8];
#pragma unroll
    for (int g = 0; g < 4; g++) {
        const float* W0 = Ws[g] + (size_t)u0 * 512 + 256;
        const float* W1 = Ws[g] + (size_t)(u0 + 1) * 512 + 256;
#pragma unroll
        for (int j = 0; j < 8; j++) {
            int k = lane * 8 + j;
            PACK2(wp[g][j], W0[k], W1[k]);
        }
    }

    const bool hi4 = (lane & 16) != 0;
    const bool hi3 = (lane & 8) != 0;
    const int  gsel = 2 * (int)hi4 + (int)hi3;   // gate this lane-class reports

    float2 cst = {0.f, 0.f};

    for (int t = 0; t < TT; t++) {
        // Prefetch Z (independent of h) before waiting on flags
        float2 zf, zi, zg, zo;
        if (tid < 64) {
            const float* zr = g_Z + ((size_t)t * 64 + tid) * 1024 + u0;
            zf = __ldcs((const float2*)(zr));
            zi = __ldcs((const float2*)(zr + 256));
            zg = __ldcs((const float2*)(zr + 512));
            zo = __ldcs((const float2*)(zr + 768));
        }

        if (t > 0) {
            // Acquire: each of threads 0..127 polls its OWN flag line
            if (tid < NBLK) {
                const unsigned* fp = &g_flags[tid * FPAD];
                unsigned vv;
                do {
                    asm volatile("ld.acquire.gpu.global.u32 %0, [%1];"
                                 : "=r"(vv) : "l"(fp) : "memory");
                } while (vv < (unsigned)t);
            }
            __syncthreads();

            // ---- stage h -> SMEM, linear coalesced (8 LDG.128 / thread) ----
            const float4* hsrc = (const float4*)&g_h[t & 1][0];
            float4*       hdst = (float4*)hs;
#pragma unroll
            for (int i = 0; i < 8; i++) {
                int f4 = tid + i * 512;               // 4096 float4 total
                hdst[f4] = __ldcg(&hsrc[f4]);
            }
            __syncthreads();

            // ---- compute 4 batches for this warp ----
#pragma unroll
            for (int b4 = 0; b4 < 4; b4++) {
                int bb = warp * 4 + b4;
                const float4* hb = (const float4*)&hs[bb * 256 + lane * 8];
                float4 ha = hb[0];
                float4 hc = hb[1];

                ull acc0 = 0, acc1 = 0, acc2v = 0, acc3 = 0;
                ull hd;
                PACK2(hd, ha.x, ha.x);
                FMA_F32X2(acc0, wp[0][0], hd, acc0);
                FMA_F32X2(acc1, wp[1][0], hd, acc1);
                FMA_F32X2(acc2v, wp[2][0], hd, acc2v);
                FMA_F32X2(acc3, wp[3][0], hd, acc3);
                PACK2(hd, ha.y, ha.y);
                FMA_F32X2(acc0, wp[0][1], hd, acc0);
                FMA_F32X2(acc1, wp[1][1], hd, acc1);
                FMA_F32X2(acc2v, wp[2][1], hd, acc2v);
                FMA_F32X2(acc3, wp[3][1], hd, acc3);
                PACK2(hd, ha.z, ha.z);
                FMA_F32X2(acc0, wp[0][2], hd, acc0);
                FMA_F32X2(acc1, wp[1][2], hd, acc1);
                FMA_F32X2(acc2v, wp[2][2], hd, acc2v);
                FMA_F32X2(acc3, wp[3][2], hd, acc3);
                PACK2(hd, ha.w, ha.w);
                FMA_F32X2(acc0, wp[0][3], hd, acc0);
                FMA_F32X2(acc1, wp[1][3], hd, acc1);
                FMA_F32X2(acc2v, wp[2][3], hd, acc2v);
                FMA_F32X2(acc3, wp[3][3], hd, acc3);
                PACK2(hd, hc.x, hc.x);
                FMA_F32X2(acc0, wp[0][4], hd, acc0);
                FMA_F32X2(acc1, wp[1][4], hd, acc1);
                FMA_F32X2(acc2v, wp[2][4], hd, acc2v);
                FMA_F32X2(acc3, wp[3][4], hd, acc3);
                PACK2(hd, hc.y, hc.y);
                FMA_F32X2(acc0, wp[0][5], hd, acc0);
                FMA_F32X2(acc1, wp[1][5], hd, acc1);
                FMA_F32X2(acc2v, wp[2][5], hd, acc2v);
                FMA_F32X2(acc3, wp[3][5], hd, acc3);
                PACK2(hd, hc.z, hc.z);
                FMA_F32X2(acc0, wp[0][6], hd, acc0);
                FMA_F32X2(acc1, wp[1][6], hd, acc1);
                FMA_F32X2(acc2v, wp[2][6], hd, acc2v);
                FMA_F32X2(acc3, wp[3][6], hd, acc3);
                PACK2(hd, hc.w, hc.w);
                FMA_F32X2(acc0, wp[0][7], hd, acc0);
                FMA_F32X2(acc1, wp[1][7], hd, acc1);
                FMA_F32X2(acc2v, wp[2][7], hd, acc2v);
                FMA_F32X2(acc3, wp[3][7], hd, acc3);

                // ---- distributing fold ----
                ull s, r, kkp, v0, v1;
                s = hi4 ? acc0 : acc2v;
                r = __shfl_xor_sync(0xffffffffu, s, 16);
                kkp = hi4 ? acc2v : acc0;
                ADD_F32X2(v0, kkp, r);
                s = hi4 ? acc1 : acc3;
                r = __shfl_xor_sync(0xffffffffu, s, 16);
                kkp = hi4 ? acc3 : acc1;
                ADD_F32X2(v1, kkp, r);
                s = hi3 ? v0 : v1;
                r = __shfl_xor_sync(0xffffffffu, s, 8);
                kkp = hi3 ? v1 : v0;
                ADD_F32X2(v0, kkp, r);
                r = __shfl_xor_sync(0xffffffffu, v0, 4);  ADD_F32X2(v0, v0, r);
                r = __shfl_xor_sync(0xffffffffu, v0, 2);  ADD_F32X2(v0, v0, r);
                r = __shfl_xor_sync(0xffffffffu, v0, 1);  ADD_F32X2(v0, v0, r);

                if ((lane & 7) == 0) {
                    float lo, hi;
                    UNPACK2(lo, hi, v0);
                    pre[(2 * gsel + 0) * 65 + bb] = lo;
                    pre[(2 * gsel + 1) * 65 + bb] = hi;
                }
            }
        } else {
            if (tid < 64) {
#pragma unroll
                for (int cc = 0; cc < 8; cc++) pre[cc * 65 + tid] = 0.f;
            }
        }
        __syncthreads();

        if (tid < 64) {
            const int b_e = tid;
            float f0 = sig_ (pre[0 * 65 + b_e] + zf.x);
            float f1 = sig_ (pre[1 * 65 + b_e] + zf.y);
            float i0 = sig_ (pre[2 * 65 + b_e] + zi.x);
            float i1 = sig_ (pre[3 * 65 + b_e] + zi.y);
            float g0 = tanh_(pre[4 * 65 + b_e] + zg.x);
            float g1 = tanh_(pre[5 * 65 + b_e] + zg.y);
            float o0 = sig_ (pre[6 * 65 + b_e] + zo.x);
            float o1 = sig_ (pre[7 * 65 + b_e] + zo.y);
            cst.x = f0 * cst.x + i0 * g0;
            cst.y = f1 * cst.y + i1 * g1;
            float h0 = o0 * tanh_(cst.x);
            float h1 = o1 * tanh_(cst.y);
            float2 h2 = {h0, h1};
            *(float2*)&g_h[(t + 1) & 1][b_e * 256 + u0]       = h2;
            *(float2*)&out[((size_t)t * 64 + b_e) * 256 + u0] = h2;
            if (t == TT - 1) {
                *(float2*)&out[TBH + b_e * 256 + u0]      = h2;
                *(float2*)&out[TBH + BH + b_e * 256 + u0] = cst;
            }
        }

        __syncthreads();     // h stores done before release
        if (tid == 0) {
            asm volatile("st.release.gpu.global.u32 [%0], %1;"
                         :: "l"(&g_flags[blk * FPAD]), "r"((unsigned)(t + 1))
                         : "memory");
        }
    }
}

// ---------------------------------------------------------------------------
// Launch
// ---------------------------------------------------------------------------
extern "C" void kernel_launch(void* const* d_in, const int* in_sizes, int n_in,
                              void* d_out, int out_size)
{
    const float* x  = (const float*)d_in[0];
    const float* Wf = (const float*)d_in[1];
    const float* bf = (const float*)d_in[2];
    const float* Wi = (const float*)d_in[3];
    const float* bi = (const float*)d_in[4];
    const float* Wg = (const float*)d_in[5];
    const float* bg = (const float*)d_in[6];
    const float* Wo = (const float*)d_in[7];
    const float* bo = (const float*)d_in[8];
    float* out = (float*)d_out;

    static bool attr_set = false;
    if (!attr_set) {
        cudaFuncSetAttribute(lstm_kernel,
                             cudaFuncAttributeMaxDynamicSharedMemorySize,
                             SMEM_FLOATS * (int)sizeof(float));
        attr_set = true;
    }

    proj_kernel<<<dim3(8, 512), 256>>>(x, Wf, bf, Wi, bi, Wg, bg, Wo, bo);
    lstm_kernel<<<NBLK, 512, SMEM_FLOATS * sizeof(float)>>>(Wf, Wi, Wg, Wo, out);
}

// round 8
// speedup vs baseline: 1.4632x; 1.4632x over previous
#include <cuda_runtime.h>
#include <cuda_bf16.h>
#include <cstdint>

#define TT   1024
#define BSZ  64
#define DD   256
#define HH   256
#define G4   1024            // 4*H
#define TBH  (TT*BSZ*HH)
#define BH   (BSZ*HH)
#define NCTA 128             // 16 clusters x 8 CTAs
#define CLU  8

typedef unsigned long long ull;

// Scratch (device globals: no runtime allocation allowed)
__device__ float g_Z[(size_t)TT * BSZ * G4];   // [t][b][gate*256+u]  (256 MB)

#define FMA_F32X2(d, a, b, c) \
    asm("fma.rn.f32x2 %0, %1, %2, %3;" : "=l"(d) : "l"(a), "l"(b), "l"(c))
#define ADD_F32X2(d, a, b) \
    asm("add.rn.f32x2 %0, %1, %2;" : "=l"(d) : "l"(a), "l"(b))
#define PACK2(d, lo, hi) \
    asm("mov.b64 %0, {%1, %2};" : "=l"(d) : "f"(lo), "f"(hi))
#define UNPACK2(lo, hi, s) \
    asm("mov.b64 {%0, %1}, %2;" : "=f"(lo), "=f"(hi) : "l"(s))

// ---------------------------------------------------------------------------
// Phase 1: Z[t][b][g*256+u] = bias_g[u] + sum_k x[t][b][k] * W_g[u*512 + k]
// GEMM M=65536 (t*64+b), N=1024, K=256. BM=128, BN=128, BK=16, 8x8 tiles.
// ---------------------------------------------------------------------------
__global__ __launch_bounds__(256, 2)
void proj_kernel(const float* __restrict__ x,
                 const float* __restrict__ Wf, const float* __restrict__ bf,
                 const float* __restrict__ Wi, const float* __restrict__ bi,
                 const float* __restrict__ Wg, const float* __restrict__ bg,
                 const float* __restrict__ Wo, const float* __restrict__ bo)
{
    __shared__ float As[16 * 132];
    __shared__ float Bs[16 * 132];

    const int tid = threadIdx.x;
    const int tx  = tid & 15;
    const int ty  = tid >> 4;
    const int bm    = blockIdx.y * 128;
    const int gate  = blockIdx.x >> 1;
    const int ucol0 = (blockIdx.x & 1) * 128;

    const float* W    = (gate == 0) ? Wf : (gate == 1) ? Wi : (gate == 2) ? Wg : Wo;
    const float* bias = (gate == 0) ? bf : (gate == 1) ? bi : (gate == 2) ? bg : bo;

    float acc[8][8];
#pragma unroll
    for (int i = 0; i < 8; i++)
#pragma unroll
        for (int j = 0; j < 8; j++) acc[i][j] = 0.f;

    for (int k0 = 0; k0 < 256; k0 += 16) {
#pragma unroll
        for (int it = 0; it < 2; it++) {
            int f4  = tid + it * 256;          // 512 float4 per tile
            int row = f4 >> 2;                 // 0..127
            int kc  = (f4 & 3) << 2;           // 0,4,8,12
            float4 av = *(const float4*)(x + (size_t)(bm + row) * 256 + k0 + kc);
            As[(kc + 0) * 132 + row] = av.x;
            As[(kc + 1) * 132 + row] = av.y;
            As[(kc + 2) * 132 + row] = av.z;
            As[(kc + 3) * 132 + row] = av.w;
            float4 bv = *(const float4*)(W + (size_t)(ucol0 + row) * 512 + k0 + kc);
            Bs[(kc + 0) * 132 + row] = bv.x;
            Bs[(kc + 1) * 132 + row] = bv.y;
            Bs[(kc + 2) * 132 + row] = bv.z;
            Bs[(kc + 3) * 132 + row] = bv.w;
        }
        __syncthreads();
#pragma unroll
        for (int kk = 0; kk < 16; kk++) {
            float4 a0 = *(const float4*)&As[kk * 132 + ty * 8];
            float4 a1 = *(const float4*)&As[kk * 132 + ty * 8 + 4];
            float4 b0 = *(const float4*)&Bs[kk * 132 + tx * 8];
            float4 b1 = *(const float4*)&Bs[kk * 132 + tx * 8 + 4];
            float a[8] = {a0.x, a0.y, a0.z, a0.w, a1.x, a1.y, a1.z, a1.w};
            float b[8] = {b0.x, b0.y, b0.z, b0.w, b1.x, b1.y, b1.z, b1.w};
#pragma unroll
            for (int i = 0; i < 8; i++)
#pragma unroll
                for (int j = 0; j < 8; j++) acc[i][j] += a[i] * b[j];
        }
        __syncthreads();
    }

    float4 q0 = *(const float4*)(bias + ucol0 + tx * 8);
    float4 q1 = *(const float4*)(bias + ucol0 + tx * 8 + 4);
    float bb[8] = {q0.x, q0.y, q0.z, q0.w, q1.x, q1.y, q1.z, q1.w};

#pragma unroll
    for (int i = 0; i < 8; i++) {
        size_t m  = (size_t)(bm + ty * 8 + i);
        float* zp = g_Z + m * 1024 + gate * 256 + ucol0 + tx * 8;
        float4 v0 = {acc[i][0] + bb[0], acc[i][1] + bb[1], acc[i][2] + bb[2], acc[i][3] + bb[3]};
        float4 v1 = {acc[i][4] + bb[4], acc[i][5] + bb[5], acc[i][6] + bb[6], acc[i][7] + bb[7]};
        *(float4*)zp       = v0;
        *(float4*)(zp + 4) = v1;
    }
}

// ---------------------------------------------------------------------------
// Phase 2: cluster-local recurrence. 16 clusters x 8 CTAs x 512 threads.
// Cluster cid owns batches [4*cid, 4*cid+4). CTA rank r owns hidden units
// [32r, 32r+32) = 128 gate cols (col = uu*4 + gate). No global sync at all:
// h lives in per-CTA SMEM (full 256 units x 4 batches, double buffered),
// exchanged via DSMEM pushes + ONE cluster.sync per step.
//   warp w: kq = w>>2 (k-range 64), cg = w&3 (cols [32cg,32cg+32)), lane=col.
//   Weights as f32x2 k-pairs in regs (wk[32] = 64 regs). h read from SMEM
//   broadcast (LDS.128), 32 FFMA2 per (batch,thread). 4-way kq reduction
//   through SMEM partials. Epilogue on 128 threads, h pushed to all 8 CTAs.
// ---------------------------------------------------------------------------
__device__ __forceinline__ float sig_(float v)  { return __fdividef(1.f, 1.f + __expf(-v)); }
__device__ __forceinline__ float tanh_(float v) { return __fdividef(2.f, 1.f + __expf(-2.f * v)) - 1.f; }

__device__ __forceinline__ uint32_t smem_u32(const void* p) {
    uint32_t a;
    asm("{ .reg .u64 t; cvta.to.shared.u64 t, %1; cvt.u32.u64 %0, t; }"
        : "=r"(a) : "l"(p));
    return a;
}

__device__ __forceinline__ void push_h(uint32_t laddr, int rank, float v) {
    uint32_t ra;
    asm("mapa.shared::cluster.u32 %0, %1, %2;" : "=r"(ra) : "r"(laddr), "r"(rank));
    asm volatile("st.shared::cluster.f32 [%0], %1;" :: "r"(ra), "f"(v));
}

#define CLUSTER_SYNC_() do { \
    asm volatile("barrier.cluster.arrive.aligned;" ::: "memory"); \
    asm volatile("barrier.cluster.wait.aligned;"   ::: "memory"); \
} while (0)

__global__ __launch_bounds__(512, 1)
void lstm_kernel(const float* __restrict__ Wf, const float* __restrict__ Wi,
                 const float* __restrict__ Wg, const float* __restrict__ Wo,
                 float* __restrict__ out)
{
    __shared__ float hs[2][4][256];     // [buf][bq][k]  (8KB)
    __shared__ float pre4[4][4][128];   // [bq][kq][col] (8KB)

    const int tid  = threadIdx.x;
    const int lane = tid & 31;
    const int w    = tid >> 5;
    const int kq   = w >> 2;            // k-quarter
    const int cg   = w & 3;             // col-group
    const int lc   = cg * 32 + lane;    // local col 0..127

    uint32_t rank;
    asm("mov.u32 %0, %%cluster_ctarank;" : "=r"(rank));
    const int cid = blockIdx.x >> 3;
    const int b0  = cid * 4;

    // ---- recurrent weights: this thread's col, k in [64kq, 64kq+64) ----
    const int uu = lc >> 2;
    const int gt = lc & 3;
    const float* Ws[4] = {Wf, Wi, Wg, Wo};
    const ull* wrow = (const ull*)(Ws[gt] + (size_t)(rank * 32 + uu) * 512 + 256 + kq * 64);
    ull wk[32];
#pragma unroll
    for (int j = 0; j < 32; j++) wk[j] = wrow[j];

    // zero h buffers
    for (int i = tid; i < 2 * 4 * 256; i += 512) ((float*)hs)[i] = 0.f;

    // epilogue identity (threads 0..127): bq = tid>>5, uue = tid&31
    const int bq_e  = tid >> 5;
    const int uu_e  = tid & 31;
    const int bg_e  = b0 + bq_e;                 // global batch
    const int ug_e  = (int)rank * 32 + uu_e;     // global unit
    const uint32_t haddr0 = smem_u32(&hs[0][bq_e][ug_e]);
    const uint32_t haddr1 = smem_u32(&hs[1][bq_e][ug_e]);
    float cstate = 0.f;

    CLUSTER_SYNC_();   // hs zero visible cluster-wide before first step

    for (int t = 0; t < TT; t++) {
        // Z prefetch (consumed by epilogue ~1500cyc later)
        float z0, z1, z2, z3;
        if (tid < 128) {
            const float* zr = g_Z + ((size_t)t * 64 + bg_e) * 1024 + ug_e;
            z0 = __ldcs(zr);
            z1 = __ldcs(zr + 256);
            z2 = __ldcs(zr + 512);
            z3 = __ldcs(zr + 768);
        }

        // ---- GEMM: 4 batches, this thread's col, 64 k's ----
        const int buf = t & 1;
#pragma unroll
        for (int bq = 0; bq < 4; bq++) {
            const float4* hp4 = (const float4*)&hs[buf][bq][kq * 64];  // 16 float4
            ull a0 = 0ull, a1 = 0ull;
#pragma unroll
            for (int j = 0; j < 16; j++) {
                float4 v = hp4[j];
                ull h01, h23;
                PACK2(h01, v.x, v.y);
                PACK2(h23, v.z, v.w);
                FMA_F32X2(a0, wk[2 * j + 0], h01, a0);
                FMA_F32X2(a1, wk[2 * j + 1], h23, a1);
            }
            ADD_F32X2(a0, a0, a1);
            float lo, hi;
            UNPACK2(lo, hi, a0);
            pre4[bq][kq][lc] = lo + hi;
        }
        __syncthreads();

        // ---- epilogue: 128 threads, one (batch, unit) each ----
        if (tid < 128) {
            float4 s0 = *(const float4*)&pre4[bq_e][0][uu_e * 4];
            float4 s1 = *(const float4*)&pre4[bq_e][1][uu_e * 4];
            float4 s2 = *(const float4*)&pre4[bq_e][2][uu_e * 4];
            float4 s3 = *(const float4*)&pre4[bq_e][3][uu_e * 4];
            float pf = (s0.x + s1.x) + (s2.x + s3.x);
            float pi = (s0.y + s1.y) + (s2.y + s3.y);
            float pg = (s0.z + s1.z) + (s2.z + s3.z);
            float po = (s0.w + s1.w) + (s2.w + s3.w);

            float fg = sig_ (pf + z0);
            float ig = sig_ (pi + z1);
            float gg = tanh_(pg + z2);
            float og = sig_ (po + z3);
            cstate = fg * cstate + ig * gg;
            float h = og * tanh_(cstate);

            out[((size_t)t * 64 + bg_e) * 256 + ug_e] = h;
            if (t == TT - 1) {
                out[TBH + bg_e * 256 + ug_e]      = h;
                out[TBH + BH + bg_e * 256 + ug_e] = cstate;
            }

            // push h to hs[buf^1] of ALL 8 cluster CTAs
            uint32_t ha = (buf ? haddr0 : haddr1);
#pragma unroll
            for (int r = 0; r < CLU; r++) push_h(ha, r, h);
        }

        // one cluster barrier per step: orders DSMEM pushes before next GEMM,
        // and guarantees everyone is done reading hs[buf] before it is
        // overwritten two steps later (double buffer).
        CLUSTER_SYNC_();
    }
}

// ---------------------------------------------------------------------------
// Launch
// ---------------------------------------------------------------------------
extern "C" void kernel_launch(void* const* d_in, const int* in_sizes, int n_in,
                              void* d_out, int out_size)
{
    const float* x  = (const float*)d_in[0];
    const float* Wf = (const float*)d_in[1];
    const float* bf = (const float*)d_in[2];
    const float* Wi = (const float*)d_in[3];
    const float* bi = (const float*)d_in[4];
    const float* Wg = (const float*)d_in[5];
    const float* bg = (const float*)d_in[6];
    const float* Wo = (const float*)d_in[7];
    const float* bo = (const float*)d_in[8];
    float* out = (float*)d_out;

    proj_kernel<<<dim3(8, 512), 256>>>(x, Wf, bf, Wi, bi, Wg, bg, Wo, bo);

    cudaLaunchConfig_t cfg = {};
    cfg.gridDim  = dim3(NCTA, 1, 1);
    cfg.blockDim = dim3(512, 1, 1);
    cfg.dynamicSmemBytes = 0;
    cudaLaunchAttribute attrs[1];
    attrs[0].id = cudaLaunchAttributeClusterDimension;
    attrs[0].val.clusterDim.x = CLU;
    attrs[0].val.clusterDim.y = 1;
    attrs[0].val.clusterDim.z = 1;
    cfg.attrs = attrs;
    cfg.numAttrs = 1;
    cudaLaunchKernelEx(&cfg, lstm_kernel, Wf, Wi, Wg, Wo, out);
}